// round 15
// baseline (speedup 1.0000x reference)
#include <cuda_runtime.h>
#include <math.h>

#define NPTS   65536
#define HNB    32
#define CIN    256
#define CMID   64
#define COUT   256
#define KPTS   15
#define KC     960
#define SLOPE  0.1f
#define EPSGN  1e-5f

typedef unsigned long long ull;

// ---------------- f32x2 packed-FMA helpers (FFMA2: PTX-only pattern) ----------------
__device__ __forceinline__ ull pack2(float x, float y) {
    ull r; asm("mov.b64 %0, {%1, %2};" : "=l"(r) : "f"(x), "f"(y)); return r;
}
__device__ __forceinline__ void unpack2(ull v, float &x, float &y) {
    asm("mov.b64 {%0, %1}, %2;" : "=f"(x), "=f"(y) : "l"(v));
}
__device__ __forceinline__ ull fma2(ull a, ull b, ull c) {
    ull d; asm("fma.rn.f32x2 %0, %1, %2, %3;" : "=l"(d) : "l"(a), "l"(b), "l"(c)); return d;
}

// ---------------- scratch ----------------
__device__ float g_x1[(size_t)NPTS * CMID];     // 16.7 MB (RAW unary1 out)
__device__ float g_x2[(size_t)NPTS * CMID];     // 16.7 MB (raw kpconv out)
__device__ float g_x3[(size_t)NPTS * COUT];     // 67 MB  (raw unary2 out)
__device__ float g_stats[192];                  // 3 stages x (32 sums, 32 sumsq)

__global__ void zero_stats_kernel() {
    if (threadIdx.x < 192) g_stats[threadIdx.x] = 0.f;
}

// ---------------- tiled FP32 GEMM with FFMA2, fused output-stats, optional A-side GN+leaky ----------------
// C = scale * (A @ B) + bias; A: M x K (lda), B: K x Ncols (ldb), C: M x Ncols (ldc)
// grid (M/128, Ncols/64), 256 threads, 8x4 micro-tile (as 4 row-pairs x 4 cols, f32x2-packed).
template<bool NORM_A>
__global__ __launch_bounds__(256) void gemm_kernel(
    const float* __restrict__ A, int lda,
    const float* __restrict__ B, int ldb,
    const float* __restrict__ bias,
    float* __restrict__ C, int ldc, int K, float scale,
    const float* __restrict__ nstats, const float* __restrict__ ngamma,
    const float* __restrict__ nbeta, float ninv,
    float* __restrict__ ostats, int ogshift)
{
    __shared__ __align__(16) float As[32][130];   // even stride: 8B-aligned row-pairs
    __shared__ __align__(16) float Bs[32][68];
    __shared__ float a_sc[64], a_sh[64];
    __shared__ float s_sum[64], s_sq[64];

    const int tid   = threadIdx.x;
    const int tx    = tid & 15;
    const int ty    = tid >> 4;
    const int rbase = blockIdx.x * 128;
    const int cbase = blockIdx.y * 64;
    const int r0    = ty * 8;
    const int c0    = tx * 4;

    if (tid < 64) {
        s_sum[tid] = 0.f; s_sq[tid] = 0.f;
        if (NORM_A) {                    // A channels: CMID=64, 2 ch/group
            int g = tid >> 1;
            float m  = nstats[g] * ninv;
            float va = nstats[32 + g] * ninv - m * m;
            float rs = rsqrtf(va + EPSGN);
            float ga = ngamma[tid];
            a_sc[tid] = rs * ga;
            a_sh[tid] = nbeta[tid] - m * rs * ga;
        }
    }
    __syncthreads();

    ull acc[4][4];
#pragma unroll
    for (int i = 0; i < 4; i++)
#pragma unroll
        for (int j = 0; j < 4; j++) acc[i][j] = 0ull;

    for (int kk = 0; kk < K; kk += 32) {
#pragma unroll
        for (int i = tid; i < 128 * 32; i += 256) {
            int r = i >> 5, k = i & 31;
            float v = A[(size_t)(rbase + r) * lda + (kk + k)];
            if (NORM_A) {
                int ch = kk + k;
                v = fmaf(v, a_sc[ch], a_sh[ch]);
                v = fmaxf(v, SLOPE * v);      // leaky relu
            }
            As[k][r] = v;
        }
#pragma unroll
        for (int i = tid; i < 32 * 64; i += 256) {
            int k = i >> 6, c = i & 63;
            Bs[k][c] = B[(size_t)(kk + k) * ldb + (cbase + c)];
        }
        __syncthreads();

#pragma unroll
        for (int k = 0; k < 32; k++) {
            ull a2[4];
#pragma unroll
            for (int ip = 0; ip < 4; ip++)
                a2[ip] = *(const ull*)&As[k][r0 + 2 * ip];
            float4 b4 = *(const float4*)&Bs[k][c0];
            ull b2[4];
            b2[0] = pack2(b4.x, b4.x); b2[1] = pack2(b4.y, b4.y);
            b2[2] = pack2(b4.z, b4.z); b2[3] = pack2(b4.w, b4.w);
#pragma unroll
            for (int ip = 0; ip < 4; ip++)
#pragma unroll
                for (int j = 0; j < 4; j++)
                    acc[ip][j] = fma2(a2[ip], b2[j], acc[ip][j]);
        }
        __syncthreads();
    }

    // epilogue: bias + scale, store, per-channel stats
    float4 bv = *(const float4*)&bias[cbase + c0];
    float bb[4] = {bv.x, bv.y, bv.z, bv.w};
    float s[4] = {0.f, 0.f, 0.f, 0.f}, sq[4] = {0.f, 0.f, 0.f, 0.f};
#pragma unroll
    for (int ip = 0; ip < 4; ip++) {
        float e[4], o[4];
#pragma unroll
        for (int j = 0; j < 4; j++) unpack2(acc[ip][j], e[j], o[j]);
        float4 ve, vo;
        float* pe = &ve.x; float* po = &vo.x;
#pragma unroll
        for (int j = 0; j < 4; j++) {
            float a = fmaf(e[j], scale, bb[j]);
            float b = fmaf(o[j], scale, bb[j]);
            pe[j] = a; po[j] = b;
            s[j]  += a + b;
            sq[j] = fmaf(a, a, fmaf(b, b, sq[j]));
        }
        *(float4*)&C[(size_t)(rbase + r0 + 2 * ip)     * ldc + cbase + c0] = ve;
        *(float4*)&C[(size_t)(rbase + r0 + 2 * ip + 1) * ldc + cbase + c0] = vo;
    }
#pragma unroll
    for (int j = 0; j < 4; j++) {
        atomicAdd(&s_sum[c0 + j], s[j]);
        atomicAdd(&s_sq[c0 + j], sq[j]);
    }
    __syncthreads();
    if (tid < 64) {
        int g = (cbase + tid) >> ogshift;
        atomicAdd(&ostats[g],      s_sum[tid]);
        atomicAdd(&ostats[32 + g], s_sq[tid]);
    }
}

// ---------------- fused KPConv: geometry + GN1-normalized gather-weighted + per-tile GEMM + stats ----------------
// 32 points / block, 512 threads. Dynamic smem:
//   [0, 64K)        wgt  : influence weights [1024 pairs][16] (float4-swizzled)  / aliased kpw chunk [240][64]
//   [64K, +123008)  wt   : weighted [32 pts][961]  (j = k*64 + c)
//   then idx_s[1024], kp_s[48], s_sum[64], s_sq[64], a_sc[64], a_sh[64]
#define KP_WGT_OFF   0
#define KP_WT_OFF    65536
#define KP_IDX_OFF   (65536 + 123008)
#define KP_KP_OFF    (KP_IDX_OFF + 4096)
#define KP_SUM_OFF   (KP_KP_OFF + 192)
#define KP_SQ_OFF    (KP_SUM_OFF + 256)
#define KP_ASC_OFF   (KP_SQ_OFF + 256)
#define KP_ASH_OFF   (KP_ASC_OFF + 256)
#define KP_SMEM      (KP_ASH_OFF + 256)      // 193856 bytes

__global__ __launch_bounds__(512) void kpconv_kernel(
    const float* __restrict__ q_points, const float* __restrict__ s_points,
    const int* __restrict__ nbr, const float* __restrict__ kernel_points,
    const float* __restrict__ kpw, const float* __restrict__ kpb,
    const float* __restrict__ nstats, const float* __restrict__ ngamma,
    const float* __restrict__ nbeta, float ninv,
    float* __restrict__ stats_out)
{
    extern __shared__ __align__(16) char smraw[];
    float* wgt   = (float*)(smraw + KP_WGT_OFF);
    float* wt    = (float*)(smraw + KP_WT_OFF);
    int*   idx_s = (int*)  (smraw + KP_IDX_OFF);
    float* kp_s  = (float*)(smraw + KP_KP_OFF);
    float* s_sum = (float*)(smraw + KP_SUM_OFF);
    float* s_sq  = (float*)(smraw + KP_SQ_OFF);
    float* a_sc  = (float*)(smraw + KP_ASC_OFF);
    float* a_sh  = (float*)(smraw + KP_ASH_OFF);

    const int tid = threadIdx.x;
    const int n0  = blockIdx.x * 32;

    if (tid < 45) kp_s[tid] = kernel_points[tid];
    if (tid >= 64 && tid < 192) {
        if (tid < 128) s_sum[tid - 64] = 0.f; else s_sq[tid - 128] = 0.f;
    }
    if (tid >= 192 && tid < 256) {        // GN1 scale/shift for on-the-fly normalize
        int ch = tid - 192;
        int g  = ch >> 1;
        float m  = nstats[g] * ninv;
        float va = nstats[32 + g] * ninv - m * m;
        float rs = rsqrtf(va + EPSGN);
        float ga = ngamma[ch];
        a_sc[ch] = rs * ga;
        a_sh[ch] = nbeta[ch] - m * rs * ga;
    }
    for (int i = tid; i < 1024; i += 512) idx_s[i] = nbr[n0 * HNB + i];
    __syncthreads();

    // ---- phase 0: geometry -> influence weights (float4-swizzled stores) ----
    for (int i = tid; i < 1024; i += 512) {
        int pt = i >> 5;
        int n  = n0 + pt;
        int id = idx_s[i];
        float qx = q_points[n * 3 + 0], qy = q_points[n * 3 + 1], qz = q_points[n * 3 + 2];
        float dx = s_points[(size_t)id * 3 + 0] - qx;
        float dy = s_points[(size_t)id * 3 + 1] - qy;
        float dz = s_points[(size_t)id * 3 + 2] - qz;
        float w[16];
#pragma unroll
        for (int k = 0; k < KPTS; k++) {
            float ex = dx - kp_s[3 * k + 0];
            float ey = dy - kp_s[3 * k + 1];
            float ez = dz - kp_s[3 * k + 2];
            float d  = sqrtf(fmaf(ex, ex, fmaf(ey, ey, ez * ez)));
            w[k] = fmaxf(1.0f - d, 0.0f);
        }
        w[15] = 0.f;
#pragma unroll
        for (int g = 0; g < 4; g++) {
            int slot = (g + i) & 3;   // rotate slot by pair index to spread banks
            *(float4*)&wgt[i * 16 + slot * 4] =
                make_float4(w[4 * g], w[4 * g + 1], w[4 * g + 2], w[4 * g + 3]);
        }
    }
    __syncthreads();

    // ---- phase 1: weighted[pt][k][c] = sum_h w[pt][h][k] * leaky(GN1(x1[idx][c])) (FFMA2) ----
    {
        const int c  = tid & 63;
        const int pg = tid >> 6;          // 0..7
        const float sc = a_sc[c];
        const float sh = a_sh[c];
#pragma unroll 1
        for (int m = 0; m < 4; m++) {
            int pt = pg * 4 + m;
            int ib = pt * 32;
            ull acc2[8];
#pragma unroll
            for (int t = 0; t < 8; t++) acc2[t] = 0ull;

#pragma unroll 1
            for (int h0 = 0; h0 < 32; h0 += 4) {
                float f[4];
#pragma unroll
                for (int u = 0; u < 4; u++)
                    f[u] = __ldg(&g_x1[(size_t)idx_s[ib + h0 + u] * CMID + c]);
#pragma unroll
                for (int u = 0; u < 4; u++) {
                    float y = fmaf(f[u], sc, sh);
                    y = fmaxf(y, SLOPE * y);                 // leaky relu
                    int i = ib + h0 + u;
                    ull f2 = pack2(y, y);
#pragma unroll
                    for (int j = 0; j < 4; j++) {
                        int jj = (j - i) & 3;   // k-group stored at this slot
                        ulonglong2 wv = *(const ulonglong2*)&wgt[i * 16 + j * 4];
                        acc2[2 * jj]     = fma2(wv.x, f2, acc2[2 * jj]);
                        acc2[2 * jj + 1] = fma2(wv.y, f2, acc2[2 * jj + 1]);
                    }
                }
            }
#pragma unroll
            for (int t = 0; t < 8; t++) {
                float e, o; unpack2(acc2[t], e, o);
                int k0 = 2 * t;
                wt[pt * 961 + k0 * 64 + c] = e;
                if (k0 + 1 < KPTS) wt[pt * 961 + (k0 + 1) * 64 + c] = o;
            }
        }
    }
    __syncthreads();

    // ---- phase 2: x2[pt][d] = (1/32) * sum_j wt[pt][j] * kpw[j][d] + kpb[d] ----
    {
        const int cg  = tid & 15;         // d-base = cg*4
        const int pt  = tid >> 4;         // 0..31
        ull ac0 = 0ull, ac1 = 0ull;

        for (int cc = 0; cc < 4; cc++) {
            int j0 = cc * 240;
            // stream kpw chunk into (reused) wgt region
            for (int i2 = tid; i2 < 240 * 16; i2 += 512)
                ((float4*)wgt)[i2] = ((const float4*)kpw)[j0 * 16 + i2];
            __syncthreads();
#pragma unroll 8
            for (int j = 0; j < 240; j++) {
                float wv = wt[pt * 961 + j0 + j];
                ull  w2  = pack2(wv, wv);
                ulonglong2 kv = *(const ulonglong2*)&wgt[j * 64 + cg * 4];
                ac0 = fma2(w2, kv.x, ac0);
                ac1 = fma2(w2, kv.y, ac1);
            }
            __syncthreads();
        }

        float e0, o0, e1, o1;
        unpack2(ac0, e0, o0); unpack2(ac1, e1, o1);
        int cb = cg * 4;
        float4 bv = *(const float4*)&kpb[cb];
        const float inv = 1.0f / 32.0f;
        float4 v;
        v.x = fmaf(e0, inv, bv.x);
        v.y = fmaf(o0, inv, bv.y);
        v.z = fmaf(e1, inv, bv.z);
        v.w = fmaf(o1, inv, bv.w);
        *(float4*)&g_x2[(size_t)(n0 + pt) * CMID + cb] = v;

        atomicAdd(&s_sum[cb + 0], v.x); atomicAdd(&s_sq[cb + 0], v.x * v.x);
        atomicAdd(&s_sum[cb + 1], v.y); atomicAdd(&s_sq[cb + 1], v.y * v.y);
        atomicAdd(&s_sum[cb + 2], v.z); atomicAdd(&s_sq[cb + 2], v.z * v.z);
        atomicAdd(&s_sum[cb + 3], v.w); atomicAdd(&s_sq[cb + 3], v.w * v.w);
    }
    __syncthreads();
    if (tid < 64) {
        int g = tid >> 1;
        atomicAdd(&stats_out[g],      s_sum[tid]);
        atomicAdd(&stats_out[32 + g], s_sq[tid]);
    }
}

// ---------------- final: out = leaky( GN3(x3) + s_feats ) ----------------
__global__ __launch_bounds__(256) void final_kernel(
    const float* __restrict__ x3, const float* __restrict__ stats,
    const float* __restrict__ gamma, const float* __restrict__ beta,
    const float* __restrict__ sfeats, float* __restrict__ out)
{
    __shared__ float s_mean[32], s_rstd[32];
    if (threadIdx.x < 32) {
        const float inv = 1.f / (8.f * (float)NPTS);
        float m = stats[threadIdx.x] * inv;
        float v = stats[32 + threadIdx.x] * inv - m * m;
        s_mean[threadIdx.x] = m;
        s_rstd[threadIdx.x] = rsqrtf(v + EPSGN);
    }
    __syncthreads();

    size_t total = (size_t)NPTS * COUT;
    for (size_t i = (size_t)blockIdx.x * blockDim.x + threadIdx.x;
         i < total; i += (size_t)gridDim.x * blockDim.x) {
        int ch = (int)(i & 255);
        int g  = ch >> 3;
        float y = (x3[i] - s_mean[g]) * s_rstd[g] * gamma[ch] + beta[ch] + sfeats[i];
        out[i] = fmaxf(y, SLOPE * y);
    }
}

// ---------------- launcher ----------------
extern "C" void kernel_launch(void* const* d_in, const int* in_sizes, int n_in,
                              void* d_out, int out_size)
{
    (void)in_sizes; (void)n_in; (void)out_size;
    const float* s_feats  = (const float*)d_in[0];
    const float* q_points = (const float*)d_in[1];
    const float* s_points = (const float*)d_in[2];
    const int*   nbr      = (const int*)  d_in[3];
    const float* W1       = (const float*)d_in[4];
    const float* b1       = (const float*)d_in[5];
    const float* g1       = (const float*)d_in[6];
    const float* beta1    = (const float*)d_in[7];
    const float* kpw      = (const float*)d_in[8];
    const float* kpb      = (const float*)d_in[9];
    const float* kp       = (const float*)d_in[10];
    const float* gcg      = (const float*)d_in[11];
    const float* gcb      = (const float*)d_in[12];
    const float* W2       = (const float*)d_in[13];
    const float* b2       = (const float*)d_in[14];
    const float* g2       = (const float*)d_in[15];
    const float* beta2    = (const float*)d_in[16];
    float* out = (float*)d_out;

    float *x1, *x2, *x3, *stats;
    cudaGetSymbolAddress((void**)&x1,    g_x1);
    cudaGetSymbolAddress((void**)&x2,    g_x2);
    cudaGetSymbolAddress((void**)&x3,    g_x3);
    cudaGetSymbolAddress((void**)&stats, g_stats);

    cudaFuncSetAttribute(kpconv_kernel,
                         cudaFuncAttributeMaxDynamicSharedMemorySize, KP_SMEM);

    const float invN2 = 1.f / (2.f * (float)NPTS);   // GN1/GN2: 2 channels/group

    zero_stats_kernel<<<1, 256>>>();

    // unary1: x1 = s_feats @ W1 + b1  (raw; +stats1)
    gemm_kernel<false><<<dim3(NPTS / 128, 1), 256>>>(
        s_feats, CIN, W1, CMID, b1, x1, CMID, CIN, 1.f,
        nullptr, nullptr, nullptr, 0.f, stats + 0, 1);

    // fused KPConv: GN1+leaky applied at gather; (+stats2), raw x2
    kpconv_kernel<<<2048, 512, KP_SMEM>>>(
        q_points, s_points, nbr, kp, kpw, kpb,
        stats + 0, g1, beta1, invN2, stats + 64);

    // unary2: x3 = leaky(GN2(x2)) @ W2 + b2  (GN2 fused into A-load; +stats3)
    gemm_kernel<true><<<dim3(NPTS / 128, COUT / 64), 256>>>(
        x2, CMID, W2, COUT, b2, x3, COUT, CMID, 1.f,
        stats + 64, gcg, gcb, invN2, stats + 128, 3);

    // GN3 + residual + leaky
    final_kernel<<<2048, 256>>>(x3, stats + 128, g2, beta2, s_feats, out);
}